// round 10
// baseline (speedup 1.0000x reference)
#include <cuda_runtime.h>
#include <cuda_fp16.h>
#include <math.h>

#define N_NODES 38332
#define N_EDGES (N_NODES * 32)
#define POI_LEN 38333
#define CAT_LEN 400
#define POI_DIM 300
#define CAT_DIM 100
#define D_IN 403
#define CH 64
#define GCN_LAYERS 5
#define FC1 128
#define SLOTS 96

typedef unsigned long long ull;

__device__ __forceinline__ ull pack2(float lo, float hi) {
    ull r; asm("mov.b64 %0, {%1, %2};" : "=l"(r) : "f"(lo), "f"(hi)); return r;
}
__device__ __forceinline__ void unpack2(ull v, float& lo, float& hi) {
    asm("mov.b64 {%0, %1}, %2;" : "=f"(lo), "=f"(hi) : "l"(v));
}
__device__ __forceinline__ ull ffma2(ull a, ull b, ull c) {
    ull d; asm("fma.rn.f32x2 %0, %1, %2, %3;" : "=l"(d) : "l"(a), "l"(b), "l"(c)); return d;
}
__device__ __forceinline__ unsigned su32(const void* p) {
    return (unsigned)__cvta_generic_to_shared(p);
}

// ---------------- scratch ----------------
__device__ __align__(16) __half g_featH[N_NODES * CH];
__device__ __align__(16) __half g_hs[N_NODES * CH];
__device__ __align__(16) __half g_Whi[GCN_LAYERS * CH * CH];
__device__ __align__(16) __half g_Wlo[GCN_LAYERS * CH * CH];
__device__ int   g_cnt[N_NODES];
__device__ int   g_colidx[N_NODES * SLOTS];
__device__ float g_hs1[N_NODES];
__device__ float g_fout[N_NODES];
__device__ float g_y[FC1];

// ---------------- W split ----------------
__global__ void k_wsplit(const float* __restrict__ W) {
    int i = blockIdx.x * blockDim.x + threadIdx.x;
    if (i < GCN_LAYERS * CH * CH) {
        float v = W[i];
        __half hi = __float2half_rn(v);
        float lo = v - __half2float(hi);
        g_Whi[i] = hi;
        g_Wlo[i] = __float2half_rn(lo);
    }
}

// ---------------- direct fixed-slot scatter ----------------
__global__ void k_scatter(const int* __restrict__ src, const int* __restrict__ dst) {
    int e = blockIdx.x * blockDim.x + threadIdx.x;
    if (e < N_EDGES) {
        int d = dst[e];
        int pos = atomicAdd(&g_cnt[d], 1);
        if (pos < SLOTS) g_colidx[d * SLOTS + pos] = src[e];
    }
}

// ---------------- input conv (unscaled h -> g_hs; dinv applied by k_scale) ----
#define NPB 32
#define SFP 34
#define KC 64
#define INPUT_SMEM ((D_IN * SFP + KC * CH) * 4)
__global__ void k_input(const float* __restrict__ x,
                        const float* __restrict__ poi,
                        const float* __restrict__ cat,
                        const float* __restrict__ Win) {
    extern __shared__ __align__(16) float dsm[];
    float* sf_t = dsm;
    float* sW = dsm + D_IN * SFP;
    int t = threadIdx.x;
    int warp = t >> 5, lane = t & 31;
    int node0 = blockIdx.x * NPB;

#pragma unroll
    for (int j = 0; j < 4; j++) {
        int ln = warp * 4 + j;
        int node = node0 + ln;
        if (node < N_NODES) {
            int pid = (int)x[node * 5 + 0];
            int cid = (int)x[node * 5 + 1];
            for (int k = lane; k < POI_DIM; k += 32)
                sf_t[k * SFP + ln] = poi[pid * POI_DIM + k];
            for (int k = lane; k < CAT_DIM; k += 32)
                sf_t[(POI_DIM + k) * SFP + ln] = cat[cid * CAT_DIM + k];
            if (lane < 3)
                sf_t[(POI_DIM + CAT_DIM + lane) * SFP + ln] = x[node * 5 + 2 + lane];
        } else {
            for (int k = lane; k < D_IN; k += 32) sf_t[k * SFP + ln] = 0.0f;
        }
    }
    __syncthreads();

    int p = t & 31;
    int grp = t >> 5;
    int ch0 = 2 * p;
    int ln0 = grp * 4;
    ull a00 = 0, a01 = 0, a10 = 0, a11 = 0;

    for (int kc = 0; kc < D_IN; kc += KC) {
        for (int i = t; i < KC * CH; i += 256) {
            int gi = kc * CH + i;
            sW[i] = (gi < D_IN * CH) ? Win[gi] : 0.0f;
        }
        __syncthreads();
        int kmax = D_IN - kc;
        if (kmax > KC) kmax = KC;
#pragma unroll 4
        for (int kk = 0; kk < kmax; kk++) {
            float2 w = *(const float2*)&sW[kk * CH + ch0];
            ull wp0 = pack2(w.x, w.x);
            ull wp1 = pack2(w.y, w.y);
            int k = kc + kk;
            ull f01 = *(const ull*)&sf_t[k * SFP + ln0];
            ull f23 = *(const ull*)&sf_t[k * SFP + ln0 + 2];
            a00 = ffma2(f01, wp0, a00);
            a01 = ffma2(f23, wp0, a01);
            a10 = ffma2(f01, wp1, a10);
            a11 = ffma2(f23, wp1, a11);
        }
        __syncthreads();
    }

    float c0n[4], c1n[4];
    unpack2(a00, c0n[0], c0n[1]);
    unpack2(a01, c0n[2], c0n[3]);
    unpack2(a10, c1n[0], c1n[1]);
    unpack2(a11, c1n[2], c1n[3]);
#pragma unroll
    for (int j = 0; j < 4; j++) {
        int node = node0 + ln0 + j;
        if (node < N_NODES) {
            __half2 h = __floats2half2_rn(c0n[j], c1n[j]);
            *(__half2*)&g_hs[node * CH + ch0] = h;
        }
    }
}

// ---------------- scale hs by dinv ----------------
__global__ void k_scale() {
    int i = blockIdx.x * blockDim.x + threadIdx.x;
    if (i < N_NODES * 8) {
        int node = i >> 3;
        float d = rsqrtf((float)g_cnt[node] + 1.0f);
        uint4 v = ((const uint4*)g_hs)[i];
        __half2* h = (__half2*)&v;
#pragma unroll
        for (int m = 0; m < 4; m++) {
            float2 f = __half22float2(h[m]);
            h[m] = __floats2half2_rn(f.x * d, f.y * d);
        }
        ((uint4*)g_hs)[i] = v;
    }
}

// ---------------- aggregation: warp/node, MLP=4 __ldg gathers ----------------
__global__ void k_agg(const float* __restrict__ bias, int residual,
                      const float* __restrict__ wout) {
    int warp = threadIdx.x >> 5, lane = threadIdx.x & 31;
    int node = blockIdx.x * 8 + warp;
    if (node >= N_NODES) return;
    int cnt = g_cnt[node];
    int n_nbr = cnt < SLOTS ? cnt : SLOTS;
    int base = node * SLOTS;
    int sub = lane >> 3;
    int q = lane & 7;
    const uint4* hs4 = (const uint4*)g_hs;

    float fa[8];
#pragma unroll
    for (int j = 0; j < 8; j++) fa[j] = 0.0f;

    for (int s0 = 0; s0 < n_nbr; s0 += 32) {
        int n = n_nbr - s0;
        if (n > 32) n = 32;
        int cidx = (s0 + lane < n_nbr) ? g_colidx[base + s0 + lane] : 0;
        if (n == 32) {
#pragma unroll
            for (int half = 0; half < 2; half++) {
                int i0 = 16 * half + sub * 2;
                int iA0 = __shfl_sync(0xFFFFFFFFu, cidx, i0);
                int iA1 = __shfl_sync(0xFFFFFFFFu, cidx, i0 + 1);
                int iB0 = __shfl_sync(0xFFFFFFFFu, cidx, i0 + 8);
                int iB1 = __shfl_sync(0xFFFFFFFFu, cidx, i0 + 9);
                uint4 a0 = __ldg(&hs4[iA0 * 8 + q]);
                uint4 a1 = __ldg(&hs4[iA1 * 8 + q]);
                uint4 b0 = __ldg(&hs4[iB0 * 8 + q]);
                uint4 b1 = __ldg(&hs4[iB1 * 8 + q]);
                const __half2* pa0 = (const __half2*)&a0;
                const __half2* pa1 = (const __half2*)&a1;
                const __half2* pb0 = (const __half2*)&b0;
                const __half2* pb1 = (const __half2*)&b1;
#pragma unroll
                for (int m = 0; m < 4; m++) {
                    __half2 sA = __hadd2(pa0[m], pa1[m]);
                    __half2 sB = __hadd2(pb0[m], pb1[m]);
                    float2 f1 = __half22float2(sA);
                    float2 f2 = __half22float2(sB);
                    fa[2 * m]     += f1.x + f2.x;
                    fa[2 * m + 1] += f1.y + f2.y;
                }
            }
        } else {
            int nj = (n + 7) >> 3;
            for (int j = 0; j < nj; j++) {
                int i0 = 8 * j + sub * 2;
                int i1 = i0 + 1;
                int idx0 = __shfl_sync(0xFFFFFFFFu, cidx, i0 & 31);
                int idx1 = __shfl_sync(0xFFFFFFFFu, cidx, i1 & 31);
                bool p0 = i0 < n, p1 = i1 < n;
                uint4 v0, v1;
                if (p0) v0 = __ldg(&hs4[idx0 * 8 + q]);
                if (p1) v1 = __ldg(&hs4[idx1 * 8 + q]);
                if (p0 & p1) {
                    const __half2* a = (const __half2*)&v0;
                    const __half2* b = (const __half2*)&v1;
#pragma unroll
                    for (int m = 0; m < 4; m++) {
                        __half2 s = __hadd2(a[m], b[m]);
                        float2 f = __half22float2(s);
                        fa[2 * m] += f.x; fa[2 * m + 1] += f.y;
                    }
                } else if (p0) {
                    const __half2* a = (const __half2*)&v0;
#pragma unroll
                    for (int m = 0; m < 4; m++) {
                        float2 f = __half22float2(a[m]);
                        fa[2 * m] += f.x; fa[2 * m + 1] += f.y;
                    }
                }
            }
        }
    }
#pragma unroll
    for (int j = 0; j < 8; j++) {
        fa[j] += __shfl_xor_sync(0xFFFFFFFFu, fa[j], 8);
        fa[j] += __shfl_xor_sync(0xFFFFFFFFu, fa[j], 16);
    }

    if (lane < 8) {
        uint4 sv = ((const uint4*)g_hs)[node * 8 + q];
        const __half2* sh2 = (const __half2*)&sv;
        float d = rsqrtf((float)cnt + 1.0f);
        float4 b0 = ((const float4*)bias)[q * 2];
        float4 b1 = ((const float4*)bias)[q * 2 + 1];
        float bb[8] = {b0.x, b0.y, b0.z, b0.w, b1.x, b1.y, b1.z, b1.w};
        float tv[8];
#pragma unroll
        for (int j = 0; j < 4; j++) {
            float2 f = __half22float2(sh2[j]);
            tv[2 * j]     = (fa[2 * j] + f.x) * d + bb[2 * j];
            tv[2 * j + 1] = (fa[2 * j + 1] + f.y) * d + bb[2 * j + 1];
        }
        if (wout) {
            float4 w0 = ((const float4*)wout)[q * 2];
            float4 w1 = ((const float4*)wout)[q * 2 + 1];
            float ww[8] = {w0.x, w0.y, w0.z, w0.w, w1.x, w1.y, w1.z, w1.w};
            float p = 0.0f;
#pragma unroll
            for (int j = 0; j < 8; j++) {
                float l = tv[j] >= 0.f ? tv[j] : 0.01f * tv[j];
                p = fmaf(l + tv[j], ww[j], p);
            }
            p += __shfl_down_sync(0x000000FFu, p, 4);
            p += __shfl_down_sync(0x000000FFu, p, 2);
            p += __shfl_down_sync(0x000000FFu, p, 1);
            if (lane == 0) g_hs1[node] = p * d;
        } else {
            __half2 oh[4];
#pragma unroll
            for (int j = 0; j < 4; j++) {
                float l0 = tv[2 * j] >= 0.f ? tv[2 * j] : 0.01f * tv[2 * j];
                float l1 = tv[2 * j + 1] >= 0.f ? tv[2 * j + 1] : 0.01f * tv[2 * j + 1];
                float o0 = residual ? (l0 + tv[2 * j]) : l0;
                float o1 = residual ? (l1 + tv[2 * j + 1]) : l1;
                oh[j] = __floats2half2_rn(o0, o1);
            }
            *(uint4*)&g_featH[node * CH + q * 8] = *(uint4*)oh;
        }
    }
}

// ---------------- GEMM via HMMA: grid=150, 2x128-node tiles, B staged once ----
#define SAP 72
#define GEMM_GRID 150
__global__ void k_gemm_mma(int layer) {
    __shared__ __align__(16) __half sA[128 * SAP];
    __shared__ __align__(16) __half sBh[64 * SAP];
    __shared__ __align__(16) __half sBl[64 * SAP];
    int t = threadIdx.x;
    int w = t >> 5, lane = t & 31;

    // stage B hi/lo once
    const uint4* wh = (const uint4*)(g_Whi + layer * CH * CH);
    const uint4* wl = (const uint4*)(g_Wlo + layer * CH * CH);
    for (int i = t; i < 512; i += 256) {
        int row = i >> 3, c8 = i & 7;
        *(uint4*)&sBh[row * SAP + c8 * 8] = wh[i];
        *(uint4*)&sBl[row * SAP + c8 * 8] = wl[i];
    }

#pragma unroll
    for (int tile = 0; tile < 2; tile++) {
        int node0 = (blockIdx.x * 2 + tile) * 128;

        // stage A for this tile
        for (int i = t; i < 1024; i += 256) {
            int row = i >> 3, c8 = i & 7;
            uint4 v = (node0 + row < N_NODES)
                          ? ((const uint4*)g_featH)[(node0 + row) * 8 + c8]
                          : make_uint4(0, 0, 0, 0);
            *(uint4*)&sA[row * SAP + c8 * 8] = v;
        }
        __syncthreads();

        int r0g = node0 + w * 16 + (lane >> 2);
        int r1g = r0g + 8;
        float d0 = (r0g < N_NODES) ? rsqrtf((float)g_cnt[r0g] + 1.0f) : 0.0f;
        float d1 = (r1g < N_NODES) ? rsqrtf((float)g_cnt[r1g] + 1.0f) : 0.0f;

        float acc[8][4];
#pragma unroll
        for (int nt = 0; nt < 8; nt++)
#pragma unroll
            for (int j = 0; j < 4; j++) acc[nt][j] = 0.0f;

#pragma unroll
        for (int kk = 0; kk < 4; kk++) {
            unsigned a0, a1, a2, a3;
            unsigned aaddr = su32(&sA[(w * 16 + (lane & 15)) * SAP + kk * 16 + (lane >> 4) * 8]);
            asm volatile("ldmatrix.sync.aligned.m8n8.x4.shared.b16 {%0,%1,%2,%3}, [%4];"
                         : "=r"(a0), "=r"(a1), "=r"(a2), "=r"(a3) : "r"(aaddr));
#pragma unroll
            for (int nt = 0; nt < 8; nt++) {
                unsigned bh0, bh1, bl0, bl1;
                unsigned bha = su32(&sBh[(kk * 16 + (lane & 15)) * SAP + nt * 8]);
                unsigned bla = su32(&sBl[(kk * 16 + (lane & 15)) * SAP + nt * 8]);
                asm volatile("ldmatrix.sync.aligned.m8n8.x2.trans.shared.b16 {%0,%1}, [%2];"
                             : "=r"(bh0), "=r"(bh1) : "r"(bha));
                asm volatile("ldmatrix.sync.aligned.m8n8.x2.trans.shared.b16 {%0,%1}, [%2];"
                             : "=r"(bl0), "=r"(bl1) : "r"(bla));
                asm volatile("mma.sync.aligned.m16n8k16.row.col.f32.f16.f16.f32 "
                             "{%0,%1,%2,%3}, {%4,%5,%6,%7}, {%8,%9}, {%0,%1,%2,%3};"
                             : "+f"(acc[nt][0]), "+f"(acc[nt][1]), "+f"(acc[nt][2]), "+f"(acc[nt][3])
                             : "r"(a0), "r"(a1), "r"(a2), "r"(a3), "r"(bh0), "r"(bh1));
                asm volatile("mma.sync.aligned.m16n8k16.row.col.f32.f16.f16.f32 "
                             "{%0,%1,%2,%3}, {%4,%5,%6,%7}, {%8,%9}, {%0,%1,%2,%3};"
                             : "+f"(acc[nt][0]), "+f"(acc[nt][1]), "+f"(acc[nt][2]), "+f"(acc[nt][3])
                             : "r"(a0), "r"(a1), "r"(a2), "r"(a3), "r"(bl0), "r"(bl1));
            }
        }

        int c = (lane & 3) * 2;
#pragma unroll
        for (int nt = 0; nt < 8; nt++) {
            int cc = c + nt * 8;
            if (r0g < N_NODES)
                *(__half2*)&g_hs[r0g * CH + cc] = __floats2half2_rn(acc[nt][0] * d0, acc[nt][1] * d0);
            if (r1g < N_NODES)
                *(__half2*)&g_hs[r1g * CH + cc] = __floats2half2_rn(acc[nt][2] * d1, acc[nt][3] * d1);
        }
        __syncthreads();  // protect sA before next tile's staging
    }
}

// ---------------- output aggregation ----------------
__global__ void k_outagg(const float* __restrict__ bout) {
    int warp = threadIdx.x >> 5, lane = threadIdx.x & 31;
    int node = blockIdx.x * 8 + warp;
    if (node >= N_NODES) return;
    int cnt = g_cnt[node];
    int n_nbr = cnt < SLOTS ? cnt : SLOTS;
    int base = node * SLOTS;
    float acc = (lane == 0) ? g_hs1[node] : 0.0f;
    for (int s = lane; s < n_nbr; s += 32) acc += g_hs1[g_colidx[base + s]];
#pragma unroll
    for (int o = 16; o; o >>= 1) acc += __shfl_down_sync(0xFFFFFFFFu, acc, o);
    if (lane == 0) {
        float d = rsqrtf((float)cnt + 1.0f);
        float tv = acc * d + bout[0];
        g_fout[node] = tv >= 0.f ? tv : 0.01f * tv;
    }
}

// ---------------- fc1 ----------------
__global__ void k_fc1(const float* __restrict__ W) {
    __shared__ float sh[FC1];
    int c = threadIdx.x & 127;
    int rg = threadIdx.x >> 7;
    int r0 = blockIdx.x * 128;
    float acc = 0.0f;
    int r1 = r0 + 128;
    if (r1 > N_NODES) r1 = N_NODES;
    for (int r = r0 + rg; r < r1; r += 2)
        acc = fmaf(g_fout[r], W[r * FC1 + c], acc);
    if (rg == 1) sh[c] = acc;
    __syncthreads();
    if (rg == 0) atomicAdd(&g_y[c], acc + sh[c]);
}

// ---------------- fc2 ----------------
__global__ void k_fc2(const float* __restrict__ W, const float* __restrict__ b1,
                      const float* __restrict__ b2, float* __restrict__ out) {
    __shared__ float sy[FC1];
    int t = threadIdx.x;
    if (t < FC1) {
        float v = g_y[t] + b1[t];
        sy[t] = v > 0.f ? v : 0.f;
    }
    __syncthreads();
    int j = blockIdx.x * 256 + t;
    if (j >= POI_LEN) return;
    float acc = b2[j];
#pragma unroll 8
    for (int k = 0; k < FC1; k++) acc = fmaf(sy[k], W[k * POI_LEN + j], acc);
    out[j] = acc > 0.f ? acc : 0.f;
}

// ---------------- launch ----------------
extern "C" void kernel_launch(void* const* d_in, const int* in_sizes, int n_in,
                              void* d_out, int out_size) {
    const float* x       = (const float*)d_in[0];
    const int*   eidx    = (const int*)d_in[1];
    const float* poi_emb = (const float*)d_in[2];
    const float* cat_emb = (const float*)d_in[3];
    const float* W_in    = (const float*)d_in[4];
    const float* b_in    = (const float*)d_in[5];
    const float* gcn_Ws  = (const float*)d_in[6];
    const float* gcn_bs  = (const float*)d_in[7];
    const float* W_out   = (const float*)d_in[8];
    const float* b_out   = (const float*)d_in[9];
    const float* fc1_W   = (const float*)d_in[10];
    const float* fc1_b   = (const float*)d_in[11];
    const float* fc2_W   = (const float*)d_in[12];
    const float* fc2_b   = (const float*)d_in[13];
    float* out = (float*)d_out;

    const int* src = eidx;
    const int* dst = eidx + N_EDGES;

    void* p_cnt = nullptr; void* p_y = nullptr;
    cudaGetSymbolAddress(&p_cnt, g_cnt);
    cudaGetSymbolAddress(&p_y, g_y);

    cudaFuncSetAttribute(k_input, cudaFuncAttributeMaxDynamicSharedMemorySize, INPUT_SMEM);

    cudaStream_t s1, s2;
    cudaStreamCreate(&s1);
    cudaStreamCreate(&s2);
    cudaEvent_t eFork, eJoin, eW;
    cudaEventCreateWithFlags(&eFork, cudaEventDisableTiming);
    cudaEventCreateWithFlags(&eJoin, cudaEventDisableTiming);
    cudaEventCreateWithFlags(&eW, cudaEventDisableTiming);

    cudaMemsetAsync(p_cnt, 0, N_NODES * sizeof(int));
    cudaMemsetAsync(p_y, 0, FC1 * sizeof(float));

    cudaEventRecord(eFork, 0);
    // side stream 1: input conv (independent of edges)
    cudaStreamWaitEvent(s1, eFork, 0);
    k_input<<<(N_NODES + NPB - 1) / NPB, 256, INPUT_SMEM, s1>>>(x, poi_emb, cat_emb, W_in);
    cudaEventRecord(eJoin, s1);
    // side stream 2: W split (needed only by first gemm)
    cudaStreamWaitEvent(s2, eFork, 0);
    k_wsplit<<<(GCN_LAYERS * CH * CH + 255) / 256, 256, 0, s2>>>(gcn_Ws);
    cudaEventRecord(eW, s2);

    int gbE = (N_EDGES + 255) / 256;
    k_scatter<<<gbE, 256>>>(src, dst);

    cudaStreamWaitEvent(0, eJoin, 0);
    k_scale<<<(N_NODES * 8 + 255) / 256, 256>>>();

    k_agg<<<(N_NODES + 7) / 8, 256>>>(b_in, 0, nullptr);

    cudaStreamWaitEvent(0, eW, 0);
    for (int l = 0; l < GCN_LAYERS; l++) {
        k_gemm_mma<<<GEMM_GRID, 256>>>(l);
        const float* wo = (l == GCN_LAYERS - 1) ? W_out : nullptr;
        k_agg<<<(N_NODES + 7) / 8, 256>>>(gcn_bs + l * CH, 1, wo);
    }

    k_outagg<<<(N_NODES + 7) / 8, 256>>>(b_out);

    k_fc1<<<(N_NODES + 127) / 128, 256>>>(fc1_W);
    k_fc2<<<(POI_LEN + 255) / 256, 256>>>(fc2_W, fc1_b, fc2_b, out);

    cudaEventDestroy(eFork);
    cudaEventDestroy(eJoin);
    cudaEventDestroy(eW);
    cudaStreamDestroy(s1);
    cudaStreamDestroy(s2);
}

// round 12
// speedup vs baseline: 1.0441x; 1.0441x over previous
#include <cuda_runtime.h>
#include <cuda_fp16.h>
#include <math.h>

#define N_NODES 38332
#define N_EDGES (N_NODES * 32)
#define POI_LEN 38333
#define CAT_LEN 400
#define POI_DIM 300
#define CAT_DIM 100
#define D_IN 403
#define CH 64
#define GCN_LAYERS 5
#define FC1 128
#define SLOTS 96

typedef unsigned long long ull;

__device__ __forceinline__ ull pack2(float lo, float hi) {
    ull r; asm("mov.b64 %0, {%1, %2};" : "=l"(r) : "f"(lo), "f"(hi)); return r;
}
__device__ __forceinline__ void unpack2(ull v, float& lo, float& hi) {
    asm("mov.b64 {%0, %1}, %2;" : "=f"(lo), "=f"(hi) : "l"(v));
}
__device__ __forceinline__ ull ffma2(ull a, ull b, ull c) {
    ull d; asm("fma.rn.f32x2 %0, %1, %2, %3;" : "=l"(d) : "l"(a), "l"(b), "l"(c)); return d;
}
__device__ __forceinline__ unsigned su32(const void* p) {
    return (unsigned)__cvta_generic_to_shared(p);
}

// ---------------- scratch ----------------
__device__ __align__(16) __half g_featH[N_NODES * CH];
__device__ __align__(16) __half g_hs[N_NODES * CH];
__device__ __align__(16) __half g_Whi[GCN_LAYERS * CH * CH];
__device__ __align__(16) __half g_Wlo[GCN_LAYERS * CH * CH];
__device__ int   g_cnt[N_NODES];
__device__ int   g_colidx[N_NODES * SLOTS];
__device__ float g_hs1[N_NODES];
__device__ float g_fout[N_NODES];
__device__ float g_y[FC1];
__device__ float g_sink;

// ---------------- W split ----------------
__global__ void k_wsplit(const float* __restrict__ W) {
    int i = blockIdx.x * blockDim.x + threadIdx.x;
    if (i < GCN_LAYERS * CH * CH) {
        float v = W[i];
        __half hi = __float2half_rn(v);
        float lo = v - __half2float(hi);
        g_Whi[i] = hi;
        g_Wlo[i] = __float2half_rn(lo);
    }
}

// ---------------- L2 warm-up for tail weights ----------------
__global__ void k_prefetch(const float* __restrict__ a, int n,
                           const float* __restrict__ b, int m) {
    float acc = 0.0f;
    int stride = gridDim.x * blockDim.x * 4;
    int base = (blockIdx.x * blockDim.x + threadIdx.x) * 4;
    for (int i = base; i < n; i += stride) {
        float4 v = __ldg((const float4*)(a + i));
        acc += v.x + v.y + v.z + v.w;
    }
    for (int i = base; i < m; i += stride) {
        float4 v = __ldg((const float4*)(b + i));
        acc += v.x + v.y + v.z + v.w;
    }
    if (acc == 1.0e38f) g_sink = acc;  // keeps loads alive; never taken
}

// ---------------- direct fixed-slot scatter ----------------
__global__ void k_scatter(const int* __restrict__ src, const int* __restrict__ dst) {
    int e = blockIdx.x * blockDim.x + threadIdx.x;
    if (e < N_EDGES) {
        int d = dst[e];
        int pos = atomicAdd(&g_cnt[d], 1);
        if (pos < SLOTS) g_colidx[d * SLOTS + pos] = src[e];
    }
}

// ---------------- input conv (unscaled h -> g_hs; dinv applied by k_scale) ----
#define NPB 32
#define SFP 34
#define KC 64
#define INPUT_SMEM ((D_IN * SFP + KC * CH) * 4)
__global__ void k_input(const float* __restrict__ x,
                        const float* __restrict__ poi,
                        const float* __restrict__ cat,
                        const float* __restrict__ Win) {
    extern __shared__ __align__(16) float dsm[];
    float* sf_t = dsm;
    float* sW = dsm + D_IN * SFP;
    int t = threadIdx.x;
    int warp = t >> 5, lane = t & 31;
    int node0 = blockIdx.x * NPB;

#pragma unroll
    for (int j = 0; j < 4; j++) {
        int ln = warp * 4 + j;
        int node = node0 + ln;
        if (node < N_NODES) {
            int pid = (int)x[node * 5 + 0];
            int cid = (int)x[node * 5 + 1];
            for (int k = lane; k < POI_DIM; k += 32)
                sf_t[k * SFP + ln] = poi[pid * POI_DIM + k];
            for (int k = lane; k < CAT_DIM; k += 32)
                sf_t[(POI_DIM + k) * SFP + ln] = cat[cid * CAT_DIM + k];
            if (lane < 3)
                sf_t[(POI_DIM + CAT_DIM + lane) * SFP + ln] = x[node * 5 + 2 + lane];
        } else {
            for (int k = lane; k < D_IN; k += 32) sf_t[k * SFP + ln] = 0.0f;
        }
    }
    __syncthreads();

    int p = t & 31;
    int grp = t >> 5;
    int ch0 = 2 * p;
    int ln0 = grp * 4;
    ull a00 = 0, a01 = 0, a10 = 0, a11 = 0;

    for (int kc = 0; kc < D_IN; kc += KC) {
        for (int i = t; i < KC * CH; i += 256) {
            int gi = kc * CH + i;
            sW[i] = (gi < D_IN * CH) ? Win[gi] : 0.0f;
        }
        __syncthreads();
        int kmax = D_IN - kc;
        if (kmax > KC) kmax = KC;
#pragma unroll 4
        for (int kk = 0; kk < kmax; kk++) {
            float2 w = *(const float2*)&sW[kk * CH + ch0];
            ull wp0 = pack2(w.x, w.x);
            ull wp1 = pack2(w.y, w.y);
            int k = kc + kk;
            ull f01 = *(const ull*)&sf_t[k * SFP + ln0];
            ull f23 = *(const ull*)&sf_t[k * SFP + ln0 + 2];
            a00 = ffma2(f01, wp0, a00);
            a01 = ffma2(f23, wp0, a01);
            a10 = ffma2(f01, wp1, a10);
            a11 = ffma2(f23, wp1, a11);
        }
        __syncthreads();
    }

    float c0n[4], c1n[4];
    unpack2(a00, c0n[0], c0n[1]);
    unpack2(a01, c0n[2], c0n[3]);
    unpack2(a10, c1n[0], c1n[1]);
    unpack2(a11, c1n[2], c1n[3]);
#pragma unroll
    for (int j = 0; j < 4; j++) {
        int node = node0 + ln0 + j;
        if (node < N_NODES) {
            __half2 h = __floats2half2_rn(c0n[j], c1n[j]);
            *(__half2*)&g_hs[node * CH + ch0] = h;
        }
    }
}

// ---------------- scale hs by dinv ----------------
__global__ void k_scale() {
    int i = blockIdx.x * blockDim.x + threadIdx.x;
    if (i < N_NODES * 8) {
        int node = i >> 3;
        float d = rsqrtf((float)g_cnt[node] + 1.0f);
        uint4 v = ((const uint4*)g_hs)[i];
        __half2* h = (__half2*)&v;
#pragma unroll
        for (int m = 0; m < 4; m++) {
            float2 f = __half22float2(h[m]);
            h[m] = __floats2half2_rn(f.x * d, f.y * d);
        }
        ((uint4*)g_hs)[i] = v;
    }
}

// ---------------- aggregation: warp/node, MLP=4 __ldg gathers ----------------
__global__ void k_agg(const float* __restrict__ bias, int residual,
                      const float* __restrict__ wout) {
    int warp = threadIdx.x >> 5, lane = threadIdx.x & 31;
    int node = blockIdx.x * 8 + warp;
    if (node >= N_NODES) return;
    int cnt = g_cnt[node];
    int n_nbr = cnt < SLOTS ? cnt : SLOTS;
    int base = node * SLOTS;
    int sub = lane >> 3;
    int q = lane & 7;
    const uint4* hs4 = (const uint4*)g_hs;

    float fa[8];
#pragma unroll
    for (int j = 0; j < 8; j++) fa[j] = 0.0f;

    for (int s0 = 0; s0 < n_nbr; s0 += 32) {
        int n = n_nbr - s0;
        if (n > 32) n = 32;
        int cidx = (s0 + lane < n_nbr) ? g_colidx[base + s0 + lane] : 0;
        if (n == 32) {
#pragma unroll
            for (int half = 0; half < 2; half++) {
                int i0 = 16 * half + sub * 2;
                int iA0 = __shfl_sync(0xFFFFFFFFu, cidx, i0);
                int iA1 = __shfl_sync(0xFFFFFFFFu, cidx, i0 + 1);
                int iB0 = __shfl_sync(0xFFFFFFFFu, cidx, i0 + 8);
                int iB1 = __shfl_sync(0xFFFFFFFFu, cidx, i0 + 9);
                uint4 a0 = __ldg(&hs4[iA0 * 8 + q]);
                uint4 a1 = __ldg(&hs4[iA1 * 8 + q]);
                uint4 b0 = __ldg(&hs4[iB0 * 8 + q]);
                uint4 b1 = __ldg(&hs4[iB1 * 8 + q]);
                const __half2* pa0 = (const __half2*)&a0;
                const __half2* pa1 = (const __half2*)&a1;
                const __half2* pb0 = (const __half2*)&b0;
                const __half2* pb1 = (const __half2*)&b1;
#pragma unroll
                for (int m = 0; m < 4; m++) {
                    __half2 sA = __hadd2(pa0[m], pa1[m]);
                    __half2 sB = __hadd2(pb0[m], pb1[m]);
                    float2 f1 = __half22float2(sA);
                    float2 f2 = __half22float2(sB);
                    fa[2 * m]     += f1.x + f2.x;
                    fa[2 * m + 1] += f1.y + f2.y;
                }
            }
        } else {
            int nj = (n + 7) >> 3;
            for (int j = 0; j < nj; j++) {
                int i0 = 8 * j + sub * 2;
                int i1 = i0 + 1;
                int idx0 = __shfl_sync(0xFFFFFFFFu, cidx, i0 & 31);
                int idx1 = __shfl_sync(0xFFFFFFFFu, cidx, i1 & 31);
                bool p0 = i0 < n, p1 = i1 < n;
                uint4 v0, v1;
                if (p0) v0 = __ldg(&hs4[idx0 * 8 + q]);
                if (p1) v1 = __ldg(&hs4[idx1 * 8 + q]);
                if (p0 & p1) {
                    const __half2* a = (const __half2*)&v0;
                    const __half2* b = (const __half2*)&v1;
#pragma unroll
                    for (int m = 0; m < 4; m++) {
                        __half2 s = __hadd2(a[m], b[m]);
                        float2 f = __half22float2(s);
                        fa[2 * m] += f.x; fa[2 * m + 1] += f.y;
                    }
                } else if (p0) {
                    const __half2* a = (const __half2*)&v0;
#pragma unroll
                    for (int m = 0; m < 4; m++) {
                        float2 f = __half22float2(a[m]);
                        fa[2 * m] += f.x; fa[2 * m + 1] += f.y;
                    }
                }
            }
        }
    }
#pragma unroll
    for (int j = 0; j < 8; j++) {
        fa[j] += __shfl_xor_sync(0xFFFFFFFFu, fa[j], 8);
        fa[j] += __shfl_xor_sync(0xFFFFFFFFu, fa[j], 16);
    }

    if (lane < 8) {
        uint4 sv = ((const uint4*)g_hs)[node * 8 + q];
        const __half2* sh2 = (const __half2*)&sv;
        float d = rsqrtf((float)cnt + 1.0f);
        float4 b0 = ((const float4*)bias)[q * 2];
        float4 b1 = ((const float4*)bias)[q * 2 + 1];
        float bb[8] = {b0.x, b0.y, b0.z, b0.w, b1.x, b1.y, b1.z, b1.w};
        float tv[8];
#pragma unroll
        for (int j = 0; j < 4; j++) {
            float2 f = __half22float2(sh2[j]);
            tv[2 * j]     = (fa[2 * j] + f.x) * d + bb[2 * j];
            tv[2 * j + 1] = (fa[2 * j + 1] + f.y) * d + bb[2 * j + 1];
        }
        if (wout) {
            float4 w0 = ((const float4*)wout)[q * 2];
            float4 w1 = ((const float4*)wout)[q * 2 + 1];
            float ww[8] = {w0.x, w0.y, w0.z, w0.w, w1.x, w1.y, w1.z, w1.w};
            float p = 0.0f;
#pragma unroll
            for (int j = 0; j < 8; j++) {
                float l = tv[j] >= 0.f ? tv[j] : 0.01f * tv[j];
                p = fmaf(l + tv[j], ww[j], p);
            }
            p += __shfl_down_sync(0x000000FFu, p, 4);
            p += __shfl_down_sync(0x000000FFu, p, 2);
            p += __shfl_down_sync(0x000000FFu, p, 1);
            if (lane == 0) g_hs1[node] = p * d;
        } else {
            __half2 oh[4];
#pragma unroll
            for (int j = 0; j < 4; j++) {
                float l0 = tv[2 * j] >= 0.f ? tv[2 * j] : 0.01f * tv[2 * j];
                float l1 = tv[2 * j + 1] >= 0.f ? tv[2 * j + 1] : 0.01f * tv[2 * j + 1];
                float o0 = residual ? (l0 + tv[2 * j]) : l0;
                float o1 = residual ? (l1 + tv[2 * j + 1]) : l1;
                oh[j] = __floats2half2_rn(o0, o1);
            }
            *(uint4*)&g_featH[node * CH + q * 8] = *(uint4*)oh;
        }
    }
}

// ---------------- 64x64 GEMM via HMMA, split-fp16 B (grid=300, 1 tile/block) --
#define SAP 72
__global__ void k_gemm_mma(int layer) {
    __shared__ __align__(16) __half sA[128 * SAP];
    __shared__ __align__(16) __half sBh[64 * SAP];
    __shared__ __align__(16) __half sBl[64 * SAP];
    int t = threadIdx.x;
    int w = t >> 5, lane = t & 31;
    int node0 = blockIdx.x * 128;

    for (int i = t; i < 1024; i += 256) {
        int row = i >> 3, c8 = i & 7;
        uint4 v = (node0 + row < N_NODES) ? ((const uint4*)g_featH)[(node0 + row) * 8 + c8]
                                          : make_uint4(0, 0, 0, 0);
        *(uint4*)&sA[row * SAP + c8 * 8] = v;
    }
    const uint4* wh = (const uint4*)(g_Whi + layer * CH * CH);
    const uint4* wl = (const uint4*)(g_Wlo + layer * CH * CH);
    for (int i = t; i < 512; i += 256) {
        int row = i >> 3, c8 = i & 7;
        *(uint4*)&sBh[row * SAP + c8 * 8] = wh[i];
        *(uint4*)&sBl[row * SAP + c8 * 8] = wl[i];
    }
    __syncthreads();

    int r0g = node0 + w * 16 + (lane >> 2);
    int r1g = r0g + 8;
    float d0 = (r0g < N_NODES) ? rsqrtf((float)g_cnt[r0g] + 1.0f) : 0.0f;
    float d1 = (r1g < N_NODES) ? rsqrtf((float)g_cnt[r1g] + 1.0f) : 0.0f;

    float acc[8][4];
#pragma unroll
    for (int nt = 0; nt < 8; nt++)
#pragma unroll
        for (int j = 0; j < 4; j++) acc[nt][j] = 0.0f;

#pragma unroll
    for (int kk = 0; kk < 4; kk++) {
        unsigned a0, a1, a2, a3;
        unsigned aaddr = su32(&sA[(w * 16 + (lane & 15)) * SAP + kk * 16 + (lane >> 4) * 8]);
        asm volatile("ldmatrix.sync.aligned.m8n8.x4.shared.b16 {%0,%1,%2,%3}, [%4];"
                     : "=r"(a0), "=r"(a1), "=r"(a2), "=r"(a3) : "r"(aaddr));
#pragma unroll
        for (int nt = 0; nt < 8; nt++) {
            unsigned bh0, bh1, bl0, bl1;
            unsigned bha = su32(&sBh[(kk * 16 + (lane & 15)) * SAP + nt * 8]);
            unsigned bla = su32(&sBl[(kk * 16 + (lane & 15)) * SAP + nt * 8]);
            asm volatile("ldmatrix.sync.aligned.m8n8.x2.trans.shared.b16 {%0,%1}, [%2];"
                         : "=r"(bh0), "=r"(bh1) : "r"(bha));
            asm volatile("ldmatrix.sync.aligned.m8n8.x2.trans.shared.b16 {%0,%1}, [%2];"
                         : "=r"(bl0), "=r"(bl1) : "r"(bla));
            asm volatile("mma.sync.aligned.m16n8k16.row.col.f32.f16.f16.f32 "
                         "{%0,%1,%2,%3}, {%4,%5,%6,%7}, {%8,%9}, {%0,%1,%2,%3};"
                         : "+f"(acc[nt][0]), "+f"(acc[nt][1]), "+f"(acc[nt][2]), "+f"(acc[nt][3])
                         : "r"(a0), "r"(a1), "r"(a2), "r"(a3), "r"(bh0), "r"(bh1));
            asm volatile("mma.sync.aligned.m16n8k16.row.col.f32.f16.f16.f32 "
                         "{%0,%1,%2,%3}, {%4,%5,%6,%7}, {%8,%9}, {%0,%1,%2,%3};"
                         : "+f"(acc[nt][0]), "+f"(acc[nt][1]), "+f"(acc[nt][2]), "+f"(acc[nt][3])
                         : "r"(a0), "r"(a1), "r"(a2), "r"(a3), "r"(bl0), "r"(bl1));
        }
    }

    int c = (lane & 3) * 2;
#pragma unroll
    for (int nt = 0; nt < 8; nt++) {
        int cc = c + nt * 8;
        if (r0g < N_NODES)
            *(__half2*)&g_hs[r0g * CH + cc] = __floats2half2_rn(acc[nt][0] * d0, acc[nt][1] * d0);
        if (r1g < N_NODES)
            *(__half2*)&g_hs[r1g * CH + cc] = __floats2half2_rn(acc[nt][2] * d1, acc[nt][3] * d1);
    }
}

// ---------------- output aggregation ----------------
__global__ void k_outagg(const float* __restrict__ bout) {
    int warp = threadIdx.x >> 5, lane = threadIdx.x & 31;
    int node = blockIdx.x * 8 + warp;
    if (node >= N_NODES) return;
    int cnt = g_cnt[node];
    int n_nbr = cnt < SLOTS ? cnt : SLOTS;
    int base = node * SLOTS;
    float acc = (lane == 0) ? g_hs1[node] : 0.0f;
    for (int s = lane; s < n_nbr; s += 32) acc += g_hs1[g_colidx[base + s]];
#pragma unroll
    for (int o = 16; o; o >>= 1) acc += __shfl_down_sync(0xFFFFFFFFu, acc, o);
    if (lane == 0) {
        float d = rsqrtf((float)cnt + 1.0f);
        float tv = acc * d + bout[0];
        g_fout[node] = tv >= 0.f ? tv : 0.01f * tv;
    }
}

// ---------------- fc1 ----------------
__global__ void k_fc1(const float* __restrict__ W) {
    __shared__ float sh[FC1];
    int c = threadIdx.x & 127;
    int rg = threadIdx.x >> 7;
    int r0 = blockIdx.x * 128;
    float acc = 0.0f;
    int r1 = r0 + 128;
    if (r1 > N_NODES) r1 = N_NODES;
    for (int r = r0 + rg; r < r1; r += 2)
        acc = fmaf(g_fout[r], W[r * FC1 + c], acc);
    if (rg == 1) sh[c] = acc;
    __syncthreads();
    if (rg == 0) atomicAdd(&g_y[c], acc + sh[c]);
}

// ---------------- fc2 ----------------
__global__ void k_fc2(const float* __restrict__ W, const float* __restrict__ b1,
                      const float* __restrict__ b2, float* __restrict__ out) {
    __shared__ float sy[FC1];
    int t = threadIdx.x;
    if (t < FC1) {
        float v = g_y[t] + b1[t];
        sy[t] = v > 0.f ? v : 0.f;
    }
    __syncthreads();
    int j = blockIdx.x * 256 + t;
    if (j >= POI_LEN) return;
    float acc = b2[j];
#pragma unroll 8
    for (int k = 0; k < FC1; k++) acc = fmaf(sy[k], W[k * POI_LEN + j], acc);
    out[j] = acc > 0.f ? acc : 0.f;
}

// ---------------- launch ----------------
extern "C" void kernel_launch(void* const* d_in, const int* in_sizes, int n_in,
                              void* d_out, int out_size) {
    const float* x       = (const float*)d_in[0];
    const int*   eidx    = (const int*)d_in[1];
    const float* poi_emb = (const float*)d_in[2];
    const float* cat_emb = (const float*)d_in[3];
    const float* W_in    = (const float*)d_in[4];
    const float* b_in    = (const float*)d_in[5];
    const float* gcn_Ws  = (const float*)d_in[6];
    const float* gcn_bs  = (const float*)d_in[7];
    const float* W_out   = (const float*)d_in[8];
    const float* b_out   = (const float*)d_in[9];
    const float* fc1_W   = (const float*)d_in[10];
    const float* fc1_b   = (const float*)d_in[11];
    const float* fc2_W   = (const float*)d_in[12];
    const float* fc2_b   = (const float*)d_in[13];
    float* out = (float*)d_out;

    const int* src = eidx;
    const int* dst = eidx + N_EDGES;

    void* p_cnt = nullptr; void* p_y = nullptr;
    cudaGetSymbolAddress(&p_cnt, g_cnt);
    cudaGetSymbolAddress(&p_y, g_y);

    cudaFuncSetAttribute(k_input, cudaFuncAttributeMaxDynamicSharedMemorySize, INPUT_SMEM);

    cudaStream_t s1, s2;
    cudaStreamCreate(&s1);
    cudaStreamCreate(&s2);
    cudaEvent_t eFork, eJoin, ePre;
    cudaEventCreateWithFlags(&eFork, cudaEventDisableTiming);
    cudaEventCreateWithFlags(&eJoin, cudaEventDisableTiming);
    cudaEventCreateWithFlags(&ePre, cudaEventDisableTiming);

    cudaMemsetAsync(p_cnt, 0, N_NODES * sizeof(int));
    cudaMemsetAsync(p_y, 0, FC1 * sizeof(float));

    cudaEventRecord(eFork, 0);
    // side stream 1: input conv (independent of edges)
    cudaStreamWaitEvent(s1, eFork, 0);
    k_input<<<(N_NODES + NPB - 1) / NPB, 256, INPUT_SMEM, s1>>>(x, poi_emb, cat_emb, W_in);
    cudaEventRecord(eJoin, s1);
    // side stream 2: L2 warm-up for tail weights (joined before fc1)
    cudaStreamWaitEvent(s2, eFork, 0);
    k_prefetch<<<74, 256, 0, s2>>>(fc1_W, N_NODES * FC1, fc2_W, FC1 * POI_LEN);
    cudaEventRecord(ePre, s2);

    int gbE = (N_EDGES + 255) / 256;
    k_wsplit<<<(GCN_LAYERS * CH * CH + 255) / 256, 256>>>(gcn_Ws);
    k_scatter<<<gbE, 256>>>(src, dst);

    cudaStreamWaitEvent(0, eJoin, 0);
    k_scale<<<(N_NODES * 8 + 255) / 256, 256>>>();

    k_agg<<<(N_NODES + 7) / 8, 256>>>(b_in, 0, nullptr);

    for (int l = 0; l < GCN_LAYERS; l++) {
        k_gemm_mma<<<(N_NODES + 127) / 128, 256>>>(l);
        const float* wo = (l == GCN_LAYERS - 1) ? W_out : nullptr;
        k_agg<<<(N_NODES + 7) / 8, 256>>>(gcn_bs + l * CH, 1, wo);
    }

    k_outagg<<<(N_NODES + 7) / 8, 256>>>(b_out);

    cudaStreamWaitEvent(0, ePre, 0);   // join prefetch stream (long since done)
    k_fc1<<<(N_NODES + 127) / 128, 256>>>(fc1_W);
    k_fc2<<<(POI_LEN + 255) / 256, 256>>>(fc2_W, fc1_b, fc2_b, out);

    cudaEventDestroy(eFork);
    cudaEventDestroy(eJoin);
    cudaEventDestroy(ePre);
    cudaStreamDestroy(s1);
    cudaStreamDestroy(s2);
}

// round 13
// speedup vs baseline: 1.0544x; 1.0098x over previous
#include <cuda_runtime.h>
#include <cuda_fp16.h>
#include <math.h>

#define N_NODES 38332
#define N_EDGES (N_NODES * 32)
#define POI_LEN 38333
#define CAT_LEN 400
#define POI_DIM 300
#define CAT_DIM 100
#define D_IN 403
#define CH 64
#define GCN_LAYERS 5
#define FC1 128
#define SLOTS 96

typedef unsigned long long ull;

__device__ __forceinline__ ull pack2(float lo, float hi) {
    ull r; asm("mov.b64 %0, {%1, %2};" : "=l"(r) : "f"(lo), "f"(hi)); return r;
}
__device__ __forceinline__ void unpack2(ull v, float& lo, float& hi) {
    asm("mov.b64 {%0, %1}, %2;" : "=f"(lo), "=f"(hi) : "l"(v));
}
__device__ __forceinline__ ull ffma2(ull a, ull b, ull c) {
    ull d; asm("fma.rn.f32x2 %0, %1, %2, %3;" : "=l"(d) : "l"(a), "l"(b), "l"(c)); return d;
}
__device__ __forceinline__ unsigned su32(const void* p) {
    return (unsigned)__cvta_generic_to_shared(p);
}

// ---------------- scratch ----------------
__device__ __align__(16) __half g_featH[N_NODES * CH];
__device__ __align__(16) __half g_hs[N_NODES * CH];
__device__ __align__(16) __half g_Whi[GCN_LAYERS * CH * CH];
__device__ __align__(16) __half g_Wlo[GCN_LAYERS * CH * CH];
__device__ int   g_cnt[N_NODES];
__device__ int   g_colidx[N_NODES * SLOTS];
__device__ float g_hs1[N_NODES];
__device__ float g_fout[N_NODES];
__device__ float g_y[FC1];
__device__ float g_sink;

// ---------------- W split ----------------
__global__ void k_wsplit(const float* __restrict__ W) {
    int i = blockIdx.x * blockDim.x + threadIdx.x;
    if (i < GCN_LAYERS * CH * CH) {
        float v = W[i];
        __half hi = __float2half_rn(v);
        float lo = v - __half2float(hi);
        g_Whi[i] = hi;
        g_Wlo[i] = __float2half_rn(lo);
    }
}

// ---------------- L2 warm-up for tail weights ----------------
__global__ void k_prefetch(const float* __restrict__ a, int n,
                           const float* __restrict__ b, int m) {
    float acc = 0.0f;
    int stride = gridDim.x * blockDim.x * 4;
    int base = (blockIdx.x * blockDim.x + threadIdx.x) * 4;
    for (int i = base; i < n; i += stride) {
        float4 v = __ldg((const float4*)(a + i));
        acc += v.x + v.y + v.z + v.w;
    }
    for (int i = base; i < m; i += stride) {
        float4 v = __ldg((const float4*)(b + i));
        acc += v.x + v.y + v.z + v.w;
    }
    if (acc == 1.0e38f) g_sink = acc;  // keeps loads alive; never taken
}

// ---------------- direct fixed-slot scatter ----------------
__global__ void k_scatter(const int* __restrict__ src, const int* __restrict__ dst) {
    int e = blockIdx.x * blockDim.x + threadIdx.x;
    if (e < N_EDGES) {
        int d = dst[e];
        int pos = atomicAdd(&g_cnt[d], 1);
        if (pos < SLOTS) g_colidx[d * SLOTS + pos] = src[e];
    }
}

// ---------------- input conv (unscaled h -> g_hs) ----------------
// 48 nodes/block; W_in L2 traffic cut to 82MB. dinv applied later in agg#1.
#define NPB 48
#define SFP 50
#define KC 64
#define INPUT_SMEM ((D_IN * SFP + KC * CH) * 4)
__global__ void k_input(const float* __restrict__ x,
                        const float* __restrict__ poi,
                        const float* __restrict__ cat,
                        const float* __restrict__ Win) {
    extern __shared__ __align__(16) float dsm[];
    float* sf_t = dsm;
    float* sW = dsm + D_IN * SFP;
    int t = threadIdx.x;  // 256
    int warp = t >> 5, lane = t & 31;
    int node0 = blockIdx.x * NPB;

#pragma unroll
    for (int j = 0; j < 6; j++) {
        int ln = warp * 6 + j;
        int node = node0 + ln;
        if (node < N_NODES) {
            int pid = (int)x[node * 5 + 0];
            int cid = (int)x[node * 5 + 1];
            for (int k = lane; k < POI_DIM; k += 32)
                sf_t[k * SFP + ln] = poi[pid * POI_DIM + k];
            for (int k = lane; k < CAT_DIM; k += 32)
                sf_t[(POI_DIM + k) * SFP + ln] = cat[cid * CAT_DIM + k];
            if (lane < 3)
                sf_t[(POI_DIM + CAT_DIM + lane) * SFP + ln] = x[node * 5 + 2 + lane];
        } else {
            for (int k = lane; k < D_IN; k += 32) sf_t[k * SFP + ln] = 0.0f;
        }
    }
    __syncthreads();

    int p = t & 31;
    int grp = t >> 5;       // 0..7 -> nodes grp*6 .. grp*6+5
    int ch0 = 2 * p;
    int ln0 = grp * 6;
    ull a0[3] = {0, 0, 0};  // ch0, node pairs (0,1)(2,3)(4,5)
    ull a1[3] = {0, 0, 0};  // ch0+1

    for (int kc = 0; kc < D_IN; kc += KC) {
        for (int i = t; i < KC * CH; i += 256) {
            int gi = kc * CH + i;
            sW[i] = (gi < D_IN * CH) ? Win[gi] : 0.0f;
        }
        __syncthreads();
        int kmax = D_IN - kc;
        if (kmax > KC) kmax = KC;
#pragma unroll 4
        for (int kk = 0; kk < kmax; kk++) {
            float2 w = *(const float2*)&sW[kk * CH + ch0];
            ull wp0 = pack2(w.x, w.x);
            ull wp1 = pack2(w.y, w.y);
            int k = kc + kk;
            const float* fr = &sf_t[k * SFP + ln0];
            ull f01 = *(const ull*)(fr);
            ull f23 = *(const ull*)(fr + 2);
            ull f45 = *(const ull*)(fr + 4);
            a0[0] = ffma2(f01, wp0, a0[0]);
            a0[1] = ffma2(f23, wp0, a0[1]);
            a0[2] = ffma2(f45, wp0, a0[2]);
            a1[0] = ffma2(f01, wp1, a1[0]);
            a1[1] = ffma2(f23, wp1, a1[1]);
            a1[2] = ffma2(f45, wp1, a1[2]);
        }
        __syncthreads();
    }

    float c0n[6], c1n[6];
#pragma unroll
    for (int j = 0; j < 3; j++) {
        unpack2(a0[j], c0n[2 * j], c0n[2 * j + 1]);
        unpack2(a1[j], c1n[2 * j], c1n[2 * j + 1]);
    }
#pragma unroll
    for (int j = 0; j < 6; j++) {
        int node = node0 + ln0 + j;
        if (node < N_NODES) {
            __half2 h = __floats2half2_rn(c0n[j], c1n[j]);
            *(__half2*)&g_hs[node * CH + ch0] = h;
        }
    }
}

// ---------------- aggregation: warp/node ----------------
// scale_src=1 (agg#1): hs is UNSCALED h; each gathered row is multiplied by
// rsqrtf(cnt[src]+1) in fp32; self term multiplied by own dinv.
// scale_src=0: hs already scaled (gemm output); fp16 pairwise pre-reduce.
__global__ void k_agg(const float* __restrict__ bias, int residual,
                      const float* __restrict__ wout, int scale_src) {
    int warp = threadIdx.x >> 5, lane = threadIdx.x & 31;
    int node = blockIdx.x * 8 + warp;
    if (node >= N_NODES) return;
    int cnt = g_cnt[node];
    int n_nbr = cnt < SLOTS ? cnt : SLOTS;
    int base = node * SLOTS;
    int sub = lane >> 3;
    int q = lane & 7;
    const uint4* hs4 = (const uint4*)g_hs;

    float fa[8];
#pragma unroll
    for (int j = 0; j < 8; j++) fa[j] = 0.0f;

    if (scale_src) {
        for (int s0 = 0; s0 < n_nbr; s0 += 32) {
            int n = n_nbr - s0;
            if (n > 32) n = 32;
            int cidx = (s0 + lane < n_nbr) ? g_colidx[base + s0 + lane] : 0;
            int nj = (n + 7) >> 3;
            for (int j = 0; j < nj; j++) {
                int i0 = 8 * j + sub * 2;
                int i1 = i0 + 1;
                int idx0 = __shfl_sync(0xFFFFFFFFu, cidx, i0 & 31);
                int idx1 = __shfl_sync(0xFFFFFFFFu, cidx, i1 & 31);
                bool p0 = i0 < n, p1 = i1 < n;
                uint4 v0, v1;
                int c0 = 0, c1 = 0;
                if (p0) { v0 = __ldg(&hs4[idx0 * 8 + q]); c0 = __ldg(&g_cnt[idx0]); }
                if (p1) { v1 = __ldg(&hs4[idx1 * 8 + q]); c1 = __ldg(&g_cnt[idx1]); }
                if (p0) {
                    float dv = rsqrtf((float)c0 + 1.0f);
                    const __half2* a = (const __half2*)&v0;
#pragma unroll
                    for (int m = 0; m < 4; m++) {
                        float2 f = __half22float2(a[m]);
                        fa[2 * m]     = fmaf(f.x, dv, fa[2 * m]);
                        fa[2 * m + 1] = fmaf(f.y, dv, fa[2 * m + 1]);
                    }
                }
                if (p1) {
                    float dv = rsqrtf((float)c1 + 1.0f);
                    const __half2* a = (const __half2*)&v1;
#pragma unroll
                    for (int m = 0; m < 4; m++) {
                        float2 f = __half22float2(a[m]);
                        fa[2 * m]     = fmaf(f.x, dv, fa[2 * m]);
                        fa[2 * m + 1] = fmaf(f.y, dv, fa[2 * m + 1]);
                    }
                }
            }
        }
    } else {
        for (int s0 = 0; s0 < n_nbr; s0 += 32) {
            int n = n_nbr - s0;
            if (n > 32) n = 32;
            int cidx = (s0 + lane < n_nbr) ? g_colidx[base + s0 + lane] : 0;
            if (n == 32) {
#pragma unroll
                for (int half = 0; half < 2; half++) {
                    int i0 = 16 * half + sub * 2;
                    int iA0 = __shfl_sync(0xFFFFFFFFu, cidx, i0);
                    int iA1 = __shfl_sync(0xFFFFFFFFu, cidx, i0 + 1);
                    int iB0 = __shfl_sync(0xFFFFFFFFu, cidx, i0 + 8);
                    int iB1 = __shfl_sync(0xFFFFFFFFu, cidx, i0 + 9);
                    uint4 a0 = __ldg(&hs4[iA0 * 8 + q]);
                    uint4 a1 = __ldg(&hs4[iA1 * 8 + q]);
                    uint4 b0 = __ldg(&hs4[iB0 * 8 + q]);
                    uint4 b1 = __ldg(&hs4[iB1 * 8 + q]);
                    const __half2* pa0 = (const __half2*)&a0;
                    const __half2* pa1 = (const __half2*)&a1;
                    const __half2* pb0 = (const __half2*)&b0;
                    const __half2* pb1 = (const __half2*)&b1;
#pragma unroll
                    for (int m = 0; m < 4; m++) {
                        __half2 sA = __hadd2(pa0[m], pa1[m]);
                        __half2 sB = __hadd2(pb0[m], pb1[m]);
                        float2 f1 = __half22float2(sA);
                        float2 f2 = __half22float2(sB);
                        fa[2 * m]     += f1.x + f2.x;
                        fa[2 * m + 1] += f1.y + f2.y;
                    }
                }
            } else {
                int nj = (n + 7) >> 3;
                for (int j = 0; j < nj; j++) {
                    int i0 = 8 * j + sub * 2;
                    int i1 = i0 + 1;
                    int idx0 = __shfl_sync(0xFFFFFFFFu, cidx, i0 & 31);
                    int idx1 = __shfl_sync(0xFFFFFFFFu, cidx, i1 & 31);
                    bool p0 = i0 < n, p1 = i1 < n;
                    uint4 v0, v1;
                    if (p0) v0 = __ldg(&hs4[idx0 * 8 + q]);
                    if (p1) v1 = __ldg(&hs4[idx1 * 8 + q]);
                    if (p0 & p1) {
                        const __half2* a = (const __half2*)&v0;
                        const __half2* b = (const __half2*)&v1;
#pragma unroll
                        for (int m = 0; m < 4; m++) {
                            __half2 s = __hadd2(a[m], b[m]);
                            float2 f = __half22float2(s);
                            fa[2 * m] += f.x; fa[2 * m + 1] += f.y;
                        }
                    } else if (p0) {
                        const __half2* a = (const __half2*)&v0;
#pragma unroll
                        for (int m = 0; m < 4; m++) {
                            float2 f = __half22float2(a[m]);
                            fa[2 * m] += f.x; fa[2 * m + 1] += f.y;
                        }
                    }
                }
            }
        }
    }
#pragma unroll
    for (int j = 0; j < 8; j++) {
        fa[j] += __shfl_xor_sync(0xFFFFFFFFu, fa[j], 8);
        fa[j] += __shfl_xor_sync(0xFFFFFFFFu, fa[j], 16);
    }

    if (lane < 8) {
        uint4 sv = ((const uint4*)g_hs)[node * 8 + q];
        const __half2* sh2 = (const __half2*)&sv;
        float d = rsqrtf((float)cnt + 1.0f);
        float ss = scale_src ? d : 1.0f;   // self term scale
        float4 b0 = ((const float4*)bias)[q * 2];
        float4 b1 = ((const float4*)bias)[q * 2 + 1];
        float bb[8] = {b0.x, b0.y, b0.z, b0.w, b1.x, b1.y, b1.z, b1.w};
        float tv[8];
#pragma unroll
        for (int j = 0; j < 4; j++) {
            float2 f = __half22float2(sh2[j]);
            tv[2 * j]     = (fa[2 * j] + f.x * ss) * d + bb[2 * j];
            tv[2 * j + 1] = (fa[2 * j + 1] + f.y * ss) * d + bb[2 * j + 1];
        }
        if (wout) {
            float4 w0 = ((const float4*)wout)[q * 2];
            float4 w1 = ((const float4*)wout)[q * 2 + 1];
            float ww[8] = {w0.x, w0.y, w0.z, w0.w, w1.x, w1.y, w1.z, w1.w};
            float p = 0.0f;
#pragma unroll
            for (int j = 0; j < 8; j++) {
                float l = tv[j] >= 0.f ? tv[j] : 0.01f * tv[j];
                p = fmaf(l + tv[j], ww[j], p);
            }
            p += __shfl_down_sync(0x000000FFu, p, 4);
            p += __shfl_down_sync(0x000000FFu, p, 2);
            p += __shfl_down_sync(0x000000FFu, p, 1);
            if (lane == 0) g_hs1[node] = p * d;
        } else {
            __half2 oh[4];
#pragma unroll
            for (int j = 0; j < 4; j++) {
                float l0 = tv[2 * j] >= 0.f ? tv[2 * j] : 0.01f * tv[2 * j];
                float l1 = tv[2 * j + 1] >= 0.f ? tv[2 * j + 1] : 0.01f * tv[2 * j + 1];
                float o0 = residual ? (l0 + tv[2 * j]) : l0;
                float o1 = residual ? (l1 + tv[2 * j + 1]) : l1;
                oh[j] = __floats2half2_rn(o0, o1);
            }
            *(uint4*)&g_featH[node * CH + q * 8] = *(uint4*)oh;
        }
    }
}

// ---------------- 64x64 GEMM via HMMA, split-fp16 B (grid=300) ----------------
#define SAP 72
__global__ void k_gemm_mma(int layer) {
    __shared__ __align__(16) __half sA[128 * SAP];
    __shared__ __align__(16) __half sBh[64 * SAP];
    __shared__ __align__(16) __half sBl[64 * SAP];
    int t = threadIdx.x;
    int w = t >> 5, lane = t & 31;
    int node0 = blockIdx.x * 128;

    for (int i = t; i < 1024; i += 256) {
        int row = i >> 3, c8 = i & 7;
        uint4 v = (node0 + row < N_NODES) ? ((const uint4*)g_featH)[(node0 + row) * 8 + c8]
                                          : make_uint4(0, 0, 0, 0);
        *(uint4*)&sA[row * SAP + c8 * 8] = v;
    }
    const uint4* wh = (const uint4*)(g_Whi + layer * CH * CH);
    const uint4* wl = (const uint4*)(g_Wlo + layer * CH * CH);
    for (int i = t; i < 512; i += 256) {
        int row = i >> 3, c8 = i & 7;
        *(uint4*)&sBh[row * SAP + c8 * 8] = wh[i];
        *(uint4*)&sBl[row * SAP + c8 * 8] = wl[i];
    }
    __syncthreads();

    int r0g = node0 + w * 16 + (lane >> 2);
    int r1g = r0g + 8;
    float d0 = (r0g < N_NODES) ? rsqrtf((float)g_cnt[r0g] + 1.0f) : 0.0f;
    float d1 = (r1g < N_NODES) ? rsqrtf((float)g_cnt[r1g] + 1.0f) : 0.0f;

    float acc[8][4];
#pragma unroll
    for (int nt = 0; nt < 8; nt++)
#pragma unroll
        for (int j = 0; j < 4; j++) acc[nt][j] = 0.0f;

#pragma unroll
    for (int kk = 0; kk < 4; kk++) {
        unsigned a0, a1, a2, a3;
        unsigned aaddr = su32(&sA[(w * 16 + (lane & 15)) * SAP + kk * 16 + (lane >> 4) * 8]);
        asm volatile("ldmatrix.sync.aligned.m8n8.x4.shared.b16 {%0,%1,%2,%3}, [%4];"
                     : "=r"(a0), "=r"(a1), "=r"(a2), "=r"(a3) : "r"(aaddr));
#pragma unroll
        for (int nt = 0; nt < 8; nt++) {
            unsigned bh0, bh1, bl0, bl1;
            unsigned bha = su32(&sBh[(kk * 16 + (lane & 15)) * SAP + nt * 8]);
            unsigned bla = su32(&sBl[(kk * 16 + (lane & 15)) * SAP + nt * 8]);
            asm volatile("ldmatrix.sync.aligned.m8n8.x2.trans.shared.b16 {%0,%1}, [%2];"
                         : "=r"(bh0), "=r"(bh1) : "r"(bha));
            asm volatile("ldmatrix.sync.aligned.m8n8.x2.trans.shared.b16 {%0,%1}, [%2];"
                         : "=r"(bl0), "=r"(bl1) : "r"(bla));
            asm volatile("mma.sync.aligned.m16n8k16.row.col.f32.f16.f16.f32 "
                         "{%0,%1,%2,%3}, {%4,%5,%6,%7}, {%8,%9}, {%0,%1,%2,%3};"
                         : "+f"(acc[nt][0]), "+f"(acc[nt][1]), "+f"(acc[nt][2]), "+f"(acc[nt][3])
                         : "r"(a0), "r"(a1), "r"(a2), "r"(a3), "r"(bh0), "r"(bh1));
            asm volatile("mma.sync.aligned.m16n8k16.row.col.f32.f16.f16.f32 "
                         "{%0,%1,%2,%3}, {%4,%5,%6,%7}, {%8,%9}, {%0,%1,%2,%3};"
                         : "+f"(acc[nt][0]), "+f"(acc[nt][1]), "+f"(acc[nt][2]), "+f"(acc[nt][3])
                         : "r"(a0), "r"(a1), "r"(a2), "r"(a3), "r"(bl0), "r"(bl1));
        }
    }

    int c = (lane & 3) * 2;
#pragma unroll
    for (int nt = 0; nt < 8; nt++) {
        int cc = c + nt * 8;
        if (r0g < N_NODES)
            *(__half2*)&g_hs[r0g * CH + cc] = __floats2half2_rn(acc[nt][0] * d0, acc[nt][1] * d0);
        if (r1g < N_NODES)
            *(__half2*)&g_hs[r1g * CH + cc] = __floats2half2_rn(acc[nt][2] * d1, acc[nt][3] * d1);
    }
}

// ---------------- output aggregation ----------------
__global__ void k_outagg(const float* __restrict__ bout) {
    int warp = threadIdx.x >> 5, lane = threadIdx.x & 31;
    int node = blockIdx.x * 8 + warp;
    if (node >= N_NODES) return;
    int cnt = g_cnt[node];
    int n_nbr = cnt < SLOTS ? cnt : SLOTS;
    int base = node * SLOTS;
    float acc = (lane == 0) ? g_hs1[node] : 0.0f;
    for (int s = lane; s < n_nbr; s += 32) acc += g_hs1[g_colidx[base + s]];
#pragma unroll
    for (int o = 16; o; o >>= 1) acc += __shfl_down_sync(0xFFFFFFFFu, acc, o);
    if (lane == 0) {
        float d = rsqrtf((float)cnt + 1.0f);
        float tv = acc * d + bout[0];
        g_fout[node] = tv >= 0.f ? tv : 0.01f * tv;
    }
}

// ---------------- fc1 ----------------
__global__ void k_fc1(const float* __restrict__ W) {
    __shared__ float sh[FC1];
    int c = threadIdx.x & 127;
    int rg = threadIdx.x >> 7;
    int r0 = blockIdx.x * 128;
    float acc = 0.0f;
    int r1 = r0 + 128;
    if (r1 > N_NODES) r1 = N_NODES;
    for (int r = r0 + rg; r < r1; r += 2)
        acc = fmaf(g_fout[r], W[r * FC1 + c], acc);
    if (rg == 1) sh[c] = acc;
    __syncthreads();
    if (rg == 0) atomicAdd(&g_y[c], acc + sh[c]);
}

// ---------------- fc2 ----------------
__global__ void k_fc2(const float* __restrict__ W, const float* __restrict__ b1,
                      const float* __restrict__ b2, float* __restrict__ out) {
    __shared__ float sy[FC1];
    int t = threadIdx.x;
    if (t < FC1) {
        float v = g_y[t] + b1[t];
        sy[t] = v > 0.f ? v : 0.f;
    }
    __syncthreads();
    int j = blockIdx.x * 256 + t;
    if (j >= POI_LEN) return;
    float acc = b2[j];
#pragma unroll 8
    for (int k = 0; k < FC1; k++) acc = fmaf(sy[k], W[k * POI_LEN + j], acc);
    out[j] = acc > 0.f ? acc : 0.f;
}

// ---------------- launch ----------------
extern "C" void kernel_launch(void* const* d_in, const int* in_sizes, int n_in,
                              void* d_out, int out_size) {
    const float* x       = (const float*)d_in[0];
    const int*   eidx    = (const int*)d_in[1];
    const float* poi_emb = (const float*)d_in[2];
    const float* cat_emb = (const float*)d_in[3];
    const float* W_in    = (const float*)d_in[4];
    const float* b_in    = (const float*)d_in[5];
    const float* gcn_Ws  = (const float*)d_in[6];
    const float* gcn_bs  = (const float*)d_in[7];
    const float* W_out   = (const float*)d_in[8];
    const float* b_out   = (const float*)d_in[9];
    const float* fc1_W   = (const float*)d_in[10];
    const float* fc1_b   = (const float*)d_in[11];
    const float* fc2_W   = (const float*)d_in[12];
    const float* fc2_b   = (const float*)d_in[13];
    float* out = (float*)d_out;

    const int* src = eidx;
    const int* dst = eidx + N_EDGES;

    void* p_cnt = nullptr; void* p_y = nullptr;
    cudaGetSymbolAddress(&p_cnt, g_cnt);
    cudaGetSymbolAddress(&p_y, g_y);

    cudaFuncSetAttribute(k_input, cudaFuncAttributeMaxDynamicSharedMemorySize, INPUT_SMEM);

    cudaStream_t s1, s2;
    cudaStreamCreate(&s1);
    cudaStreamCreate(&s2);
    cudaEvent_t eFork, eJoin, ePre;
    cudaEventCreateWithFlags(&eFork, cudaEventDisableTiming);
    cudaEventCreateWithFlags(&eJoin, cudaEventDisableTiming);
    cudaEventCreateWithFlags(&ePre, cudaEventDisableTiming);

    cudaMemsetAsync(p_cnt, 0, N_NODES * sizeof(int));
    cudaMemsetAsync(p_y, 0, FC1 * sizeof(float));

    cudaEventRecord(eFork, 0);
    // side stream 1: input conv (independent of edges)
    cudaStreamWaitEvent(s1, eFork, 0);
    k_input<<<(N_NODES + NPB - 1) / NPB, 256, INPUT_SMEM, s1>>>(x, poi_emb, cat_emb, W_in);
    cudaEventRecord(eJoin, s1);
    // side stream 2: L2 warm-up for tail weights (joined before fc1)
    cudaStreamWaitEvent(s2, eFork, 0);
    k_prefetch<<<74, 256, 0, s2>>>(fc1_W, N_NODES * FC1, fc2_W, FC1 * POI_LEN);
    cudaEventRecord(ePre, s2);

    int gbE = (N_EDGES + 255) / 256;
    k_wsplit<<<(GCN_LAYERS * CH * CH + 255) / 256, 256>>>(gcn_Ws);
    k_scatter<<<gbE, 256>>>(src, dst);

    cudaStreamWaitEvent(0, eJoin, 0);   // join input; agg#1 scales by dinv itself
    k_agg<<<(N_NODES + 7) / 8, 256>>>(b_in, 0, nullptr, 1);

    for (int l = 0; l < GCN_LAYERS; l++) {
        k_gemm_mma<<<(N_NODES + 127) / 128, 256>>>(l);
        const float* wo = (l == GCN_LAYERS - 1) ? W_out : nullptr;
        k_agg<<<(N_NODES + 7) / 8, 256>>>(gcn_bs + l * CH, 1, wo, 0);
    }

    k_outagg<<<(N_NODES + 7) / 8, 256>>>(b_out);

    cudaStreamWaitEvent(0, ePre, 0);   // join prefetch stream
    k_fc1<<<(N_NODES + 127) / 128, 256>>>(fc1_W);
    k_fc2<<<(POI_LEN + 255) / 256, 256>>>(fc2_W, fc1_b, fc2_b, out);

    cudaEventDestroy(eFork);
    cudaEventDestroy(eJoin);
    cudaEventDestroy(ePre);
    cudaStreamDestroy(s1);
    cudaStreamDestroy(s2);
}